// round 13
// baseline (speedup 1.0000x reference)
#include <cuda_runtime.h>
#include <cuda_fp16.h>

// Problem constants
#define NW      16384   // words
#define LCH     16      // chars per word
#define CEMB    64      // char emb dim
#define CO      256     // conv out channels
#define DEMB    300     // word emb dim
#define OUTW    556     // 256 + 300
#define OCHUNK  128     // channels per block (blockIdx.y in {0,1})
#define WPC     111     // words per CTA (148 * 111 >= 16384)
#define NWARPS  21      // warps per CTA (block = 672)

// Precomputed conv tables (fp16): M[k][c][o] = sum_e char_emb[c,e]*conv_w[o,e,k]
__device__ __half g_Mh[3 * 128 * 256];

// smem layout offsets (bytes)
#define SM_XPK    98304                    // WPC uint4 (packed chars)
#define SM_XW     (98304 + WPC * 16)       // WPC ints
#define SM_TOTAL  (SM_XW + WPC * 4)

// ---------------------------------------------------------------------------
// Kernel 1: build tables. grid = 256 (o), block = 128 (c).
// ---------------------------------------------------------------------------
__global__ void build_tables_kernel(const float* __restrict__ ce_w,
                                    const float* __restrict__ conv_w) {
    __shared__ float se[64 * 130];   // padded rows: no STS conflicts
    const int o = blockIdx.x;
    const int c = threadIdx.x;

    for (int i = threadIdx.x; i < 128 * 64; i += 128) {
        int cc = i >> 6;
        int e  = i & 63;
        se[e * 130 + cc] = ce_w[i];
    }
    __syncthreads();

    const float4* wp4 = reinterpret_cast<const float4*>(conv_w + o * (CEMB * 3));
    float a0 = 0.f, a1 = 0.f, a2 = 0.f;
#pragma unroll
    for (int g = 0; g < 16; ++g) {
        float4 f0 = wp4[3 * g + 0];
        float4 f1 = wp4[3 * g + 1];
        float4 f2 = wp4[3 * g + 2];
        float s0 = se[(4 * g + 0) * 130 + c];
        float s1 = se[(4 * g + 1) * 130 + c];
        float s2 = se[(4 * g + 2) * 130 + c];
        float s3 = se[(4 * g + 3) * 130 + c];
        a0 = fmaf(s0, f0.x, a0); a1 = fmaf(s0, f0.y, a1); a2 = fmaf(s0, f0.z, a2);
        a0 = fmaf(s1, f0.w, a0); a1 = fmaf(s1, f1.x, a1); a2 = fmaf(s1, f1.y, a2);
        a0 = fmaf(s2, f1.z, a0); a1 = fmaf(s2, f1.w, a1); a2 = fmaf(s2, f2.x, a2);
        a0 = fmaf(s3, f2.y, a0); a1 = fmaf(s3, f2.z, a1); a2 = fmaf(s3, f2.w, a2);
    }
    g_Mh[(0 * 128 + c) * 256 + o] = __float2half_rn(a0);
    g_Mh[(1 * 128 + c) * 256 + o] = __float2half_rn(a1);
    g_Mh[(2 * 128 + c) * 256 + o] = __float2half_rn(a2);
}

// ---------------------------------------------------------------------------
// Kernel 2: main. grid = (148, 2), block = 672, ~98.2 KB dyn smem, 2 CTAs/SM
// -> 42 warps/SM, reg cap 48 (= measured usage, no squeeze).
// R12 structure: warp=word, lane=4ch, [c][k][lane] table rows, smem-packed
// chars, dual carry chains, cp.async table staging.
// ---------------------------------------------------------------------------
struct H4 { __half2 a, b; };

__device__ __forceinline__ H4 h4add(H4 x, H4 y) {
    H4 r; r.a = __hadd2(x.a, y.a); r.b = __hadd2(x.b, y.b); return r;
}
__device__ __forceinline__ H4 h4max(H4 x, H4 y) {
    H4 r; r.a = __hmax2(x.a, y.a); r.b = __hmax2(x.b, y.b); return r;
}

extern "C" __global__ void __launch_bounds__(672, 2)
wordchar_main_kernel(const int* __restrict__ X,
                     const int* __restrict__ Xword,
                     const float* __restrict__ conv_b,
                     const float* __restrict__ wemb,
                     float* __restrict__ out) {
    extern __shared__ __align__(16) char smem_raw[];
    uint4* xs_pk4 = reinterpret_cast<uint4*>(smem_raw + SM_XPK);
    unsigned* xs_pk = reinterpret_cast<unsigned*>(smem_raw + SM_XPK);
    int* xw_s = reinterpret_cast<int*>(smem_raw + SM_XW);

    const int half_id = blockIdx.y;
    const int o_base  = half_id * OCHUNK;

    const int base = blockIdx.x * WPC;
    const int cnt  = (NW - base < WPC) ? (NW - base) : WPC;

    // ---- staging ----
    {
        // table via cp.async (no register round-trip, fully overlapped)
        const char* gbase = reinterpret_cast<const char*>(g_Mh);
        const unsigned sbase = (unsigned)__cvta_generic_to_shared(smem_raw);
        const int ntot4 = 128 * 48;            // 6144 uint4 (16B) chunks
        for (int i = threadIdx.x; i < ntot4; i += blockDim.x) {
            int c = i / 48;
            int s = i - c * 48;                // 48 uint4 per 768B char row
            int k = s >> 4;                    // 16 uint4 per k-slab
            int j = s & 15;
            const char* gsrc = gbase +
                (((size_t)(k * 128 + c) * 32 + half_id * 16 + j) * 16);
            asm volatile("cp.async.cg.shared.global [%0], [%1], 16;\n"
                         :: "r"(sbase + i * 16), "l"(gsrc));
        }
        asm volatile("cp.async.commit_group;\n" ::: "memory");

        // chars + word ids staged in the shadow of the async group
        const int4* X4 = reinterpret_cast<const int4*>(X);
        for (int i = threadIdx.x; i < cnt * 4; i += blockDim.x) {
            int4 xi = X4[base * 4 + i];        // coalesced
            xs_pk[i] = (unsigned)xi.x | ((unsigned)xi.y << 8) |
                       ((unsigned)xi.z << 16) | ((unsigned)xi.w << 24);
        }
        for (int i = threadIdx.x; i < cnt; i += blockDim.x)
            xw_s[i] = Xword[base + i];

        asm volatile("cp.async.wait_group 0;\n" ::: "memory");
    }
    __syncthreads();

    const int warp = threadIdx.x >> 5;
    const int lane = threadIdx.x & 31;

    const float4 b4 = *reinterpret_cast<const float4*>(conv_b + o_base + lane * 4);
    const char* Ms_lane = smem_raw + lane * 8;

    const int j_lo = (half_id == 0) ? 0  : 38;
    const int j_hi = (half_id == 0) ? 38 : 75;

    const H4 zero = { __float2half2_rn(0.f), __float2half2_rn(0.f) };

    for (int wl = warp; wl < cnt; wl += NWARPS) {
        const int w = base + wl;

        // chars: one broadcast LDS.128
        uint4 pkv = xs_pk4[wl];
        unsigned pk[4] = { pkv.x, pkv.y, pkv.z, pkv.w };

        // word-embedding gather kicked off early (the only LDG in the loop)
        const int wi = xw_s[wl];
        const float4* src = reinterpret_cast<const float4*>(wemb + (size_t)wi * DEMB);
        float4* dst = reinterpret_cast<float4*>(out + (size_t)w * OUTW + CO);
        float4 e0, e1;
        const int j0 = j_lo + lane;
        const int j1 = j_lo + 32 + lane;
        const bool p0 = (j0 < j_hi);
        const bool p1 = (j1 < j_hi);
        if (p0) e0 = src[j0];
        if (p1) e1 = src[j1];

        // ---- chain B warm-up: t=6,7 (m0/m1 only) ----
        H4 c0B, c1B;
        {
            const int c6 = (pk[1] >> 16) & 0xFF;
            const int c7 = (pk[1] >> 24) & 0xFF;
            const char* r6 = Ms_lane + c6 * 768;
            const char* r7 = Ms_lane + c7 * 768;
            H4 m0_6 = *reinterpret_cast<const H4*>(r6);
            H4 m1_6 = *reinterpret_cast<const H4*>(r6 + 256);
            H4 m0_7 = *reinterpret_cast<const H4*>(r7);
            H4 m1_7 = *reinterpret_cast<const H4*>(r7 + 256);
            c1B = h4add(m1_7, m0_6);   // carry into t=8
            c0B = m0_7;
        }

        // ---- interleaved dual chains: A t=i, B t=i+8 ----
        H4 maxsA, c0A = zero, c1A = zero;
        H4 maxsB;
#pragma unroll
        for (int i = 0; i < 8; ++i) {
            {
                const int cc = (pk[i >> 2] >> ((i & 3) * 8)) & 0xFF;
                const char* rowp = Ms_lane + cc * 768;
                H4 m0 = *reinterpret_cast<const H4*>(rowp);
                H4 m1 = *reinterpret_cast<const H4*>(rowp + 256);
                H4 m2 = *reinterpret_cast<const H4*>(rowp + 512);
                H4 y  = h4add(m2, c1A);
                maxsA = (i == 0) ? y : h4max(maxsA, y);
                c1A = h4add(m1, c0A);
                c0A = m0;
            }
            {
                const int t  = i + 8;
                const int cc = (pk[t >> 2] >> ((t & 3) * 8)) & 0xFF;
                const char* rowp = Ms_lane + cc * 768;
                H4 m0 = *reinterpret_cast<const H4*>(rowp);
                H4 m1 = *reinterpret_cast<const H4*>(rowp + 256);
                H4 m2 = *reinterpret_cast<const H4*>(rowp + 512);
                H4 y  = h4add(m2, c1B);
                maxsB = (i == 0) ? y : h4max(maxsB, y);
                c1B = h4add(m1, c0B);
                c0B = m0;
            }
        }
        maxsB = h4max(maxsB, c1B);   // t = 16
        maxsB = h4max(maxsB, c0B);   // t = 17
        H4 maxs = h4max(maxsA, maxsB);

        // fp32 bias + relu + store
        float2 f0 = __half22float2(maxs.a);
        float2 f1 = __half22float2(maxs.b);
        float4 r;
        r.x = fmaxf(f0.x + b4.x, 0.f);
        r.y = fmaxf(f0.y + b4.y, 0.f);
        r.z = fmaxf(f1.x + b4.z, 0.f);
        r.w = fmaxf(f1.y + b4.w, 0.f);
        *reinterpret_cast<float4*>(out + (size_t)w * OUTW + o_base + lane * 4) = r;

        if (p0) dst[j0] = e0;
        if (p1) dst[j1] = e1;
    }
}

// ---------------------------------------------------------------------------
// Launch
// ---------------------------------------------------------------------------
extern "C" void kernel_launch(void* const* d_in, const int* in_sizes, int n_in,
                              void* d_out, int out_size) {
    const int*   X        = (const int*)  d_in[0];   // [16384,16]
    const int*   X_word   = (const int*)  d_in[1];   // [16384]
    const float* char_emb = (const float*)d_in[2];   // [128,64]
    const float* conv_w   = (const float*)d_in[3];   // [256,64,3]
    const float* conv_b   = (const float*)d_in[4];   // [256]
    const float* word_emb = (const float*)d_in[5];   // [50000,300]
    float*       out      = (float*)d_out;           // [16384,556]

    build_tables_kernel<<<256, 128>>>(char_emb, conv_w);

    cudaFuncSetAttribute(wordchar_main_kernel,
                         cudaFuncAttributeMaxDynamicSharedMemorySize, SM_TOTAL);
    dim3 grid(148, 2);
    wordchar_main_kernel<<<grid, 672, SM_TOTAL>>>(X, X_word, conv_b, word_emb, out);
}

// round 14
// speedup vs baseline: 1.0707x; 1.0707x over previous
#include <cuda_runtime.h>
#include <cuda_fp16.h>

// Problem constants
#define NW      16384   // words
#define LCH     16      // chars per word
#define CEMB    64      // char emb dim
#define CO      256     // conv out channels
#define DEMB    300     // word emb dim
#define OUTW    556     // 256 + 300
#define OCHUNK  128     // channels per block (blockIdx.y in {0,1})
#define WPC     111     // words per CTA (148 * 111 >= 16384)
#define NWARPS  20      // warps per CTA (block = 640)

// Precomputed conv tables (fp16): M[k][c][o] = sum_e char_emb[c,e]*conv_w[o,e,k]
__device__ __half g_Mh[3 * 128 * 256];

// smem layout offsets (bytes)
#define SM_XPK    98304                    // WPC uint4 (packed chars)
#define SM_XW     (98304 + WPC * 16)       // WPC ints
#define SM_TOTAL  (SM_XW + WPC * 4)

// ---------------------------------------------------------------------------
// Kernel 1: build tables. grid = 256 (o), block = 128 (c).
// Triggers PDL immediately so the main kernel's prologue overlaps.
// ---------------------------------------------------------------------------
__global__ void build_tables_kernel(const float* __restrict__ ce_w,
                                    const float* __restrict__ conv_w) {
#if __CUDA_ARCH__ >= 900
    cudaTriggerProgrammaticLaunchCompletion();
#endif
    __shared__ float se[64 * 130];   // padded rows: no STS conflicts
    const int o = blockIdx.x;
    const int c = threadIdx.x;

    for (int i = threadIdx.x; i < 128 * 64; i += 128) {
        int cc = i >> 6;
        int e  = i & 63;
        se[e * 130 + cc] = ce_w[i];
    }
    __syncthreads();

    const float4* wp4 = reinterpret_cast<const float4*>(conv_w + o * (CEMB * 3));
    float a0 = 0.f, a1 = 0.f, a2 = 0.f;
#pragma unroll
    for (int g = 0; g < 16; ++g) {
        float4 f0 = wp4[3 * g + 0];
        float4 f1 = wp4[3 * g + 1];
        float4 f2 = wp4[3 * g + 2];
        float s0 = se[(4 * g + 0) * 130 + c];
        float s1 = se[(4 * g + 1) * 130 + c];
        float s2 = se[(4 * g + 2) * 130 + c];
        float s3 = se[(4 * g + 3) * 130 + c];
        a0 = fmaf(s0, f0.x, a0); a1 = fmaf(s0, f0.y, a1); a2 = fmaf(s0, f0.z, a2);
        a0 = fmaf(s1, f0.w, a0); a1 = fmaf(s1, f1.x, a1); a2 = fmaf(s1, f1.y, a2);
        a0 = fmaf(s2, f1.z, a0); a1 = fmaf(s2, f1.w, a1); a2 = fmaf(s2, f2.x, a2);
        a0 = fmaf(s3, f2.y, a0); a1 = fmaf(s3, f2.z, a1); a2 = fmaf(s3, f2.w, a2);
    }
    g_Mh[(0 * 128 + c) * 256 + o] = __float2half_rn(a0);
    g_Mh[(1 * 128 + c) * 256 + o] = __float2half_rn(a1);
    g_Mh[(2 * 128 + c) * 256 + o] = __float2half_rn(a2);
}

// ---------------------------------------------------------------------------
// Kernel 2: main. grid = (148, 2), block = 640, ~98.2 KB dyn smem, 2 CTAs/SM.
// R12 structure exactly; chars/Xword staging happens BEFORE the PDL grid
// dependency sync, table cp.async after it.
// ---------------------------------------------------------------------------
struct H4 { __half2 a, b; };

__device__ __forceinline__ H4 h4add(H4 x, H4 y) {
    H4 r; r.a = __hadd2(x.a, y.a); r.b = __hadd2(x.b, y.b); return r;
}
__device__ __forceinline__ H4 h4max(H4 x, H4 y) {
    H4 r; r.a = __hmax2(x.a, y.a); r.b = __hmax2(x.b, y.b); return r;
}

extern "C" __global__ void __launch_bounds__(640, 2)
wordchar_main_kernel(const int* __restrict__ X,
                     const int* __restrict__ Xword,
                     const float* __restrict__ conv_b,
                     const float* __restrict__ wemb,
                     float* __restrict__ out) {
    extern __shared__ __align__(16) char smem_raw[];
    uint4* xs_pk4 = reinterpret_cast<uint4*>(smem_raw + SM_XPK);
    unsigned* xs_pk = reinterpret_cast<unsigned*>(smem_raw + SM_XPK);
    int* xw_s = reinterpret_cast<int*>(smem_raw + SM_XW);

    const int half_id = blockIdx.y;
    const int o_base  = half_id * OCHUNK;

    const int base = blockIdx.x * WPC;
    const int cnt  = (NW - base < WPC) ? (NW - base) : WPC;

    // ---- prologue staging (independent of build kernel) ----
    {
        const int4* X4 = reinterpret_cast<const int4*>(X);
        for (int i = threadIdx.x; i < cnt * 4; i += blockDim.x) {
            int4 xi = X4[base * 4 + i];        // coalesced
            xs_pk[i] = (unsigned)xi.x | ((unsigned)xi.y << 8) |
                       ((unsigned)xi.z << 16) | ((unsigned)xi.w << 24);
        }
        for (int i = threadIdx.x; i < cnt; i += blockDim.x)
            xw_s[i] = Xword[base + i];
    }

#if __CUDA_ARCH__ >= 900
    cudaGridDependencySynchronize();       // wait for build_tables_kernel
#endif

    // ---- table staging via cp.async (depends on g_Mh) ----
    {
        const char* gbase = reinterpret_cast<const char*>(g_Mh);
        const unsigned sbase = (unsigned)__cvta_generic_to_shared(smem_raw);
        const int ntot4 = 128 * 48;            // 6144 uint4 (16B) chunks
        for (int i = threadIdx.x; i < ntot4; i += blockDim.x) {
            int c = i / 48;
            int s = i - c * 48;                // 48 uint4 per 768B char row
            int k = s >> 4;                    // 16 uint4 per k-slab
            int j = s & 15;
            const char* gsrc = gbase +
                (((size_t)(k * 128 + c) * 32 + half_id * 16 + j) * 16);
            asm volatile("cp.async.cg.shared.global [%0], [%1], 16;\n"
                         :: "r"(sbase + i * 16), "l"(gsrc));
        }
        asm volatile("cp.async.commit_group;\n" ::: "memory");
        asm volatile("cp.async.wait_group 0;\n" ::: "memory");
    }
    __syncthreads();

    const int warp = threadIdx.x >> 5;
    const int lane = threadIdx.x & 31;

    const float4 b4 = *reinterpret_cast<const float4*>(conv_b + o_base + lane * 4);
    const char* Ms_lane = smem_raw + lane * 8;

    const int j_lo = (half_id == 0) ? 0  : 38;
    const int j_hi = (half_id == 0) ? 38 : 75;

    const H4 zero = { __float2half2_rn(0.f), __float2half2_rn(0.f) };

    for (int wl = warp; wl < cnt; wl += NWARPS) {
        const int w = base + wl;

        // chars: one broadcast LDS.128
        uint4 pkv = xs_pk4[wl];
        unsigned pk[4] = { pkv.x, pkv.y, pkv.z, pkv.w };

        // word-embedding gather kicked off early (the only LDG in the loop)
        const int wi = xw_s[wl];
        const float4* src = reinterpret_cast<const float4*>(wemb + (size_t)wi * DEMB);
        float4* dst = reinterpret_cast<float4*>(out + (size_t)w * OUTW + CO);
        float4 e0, e1;
        const int j0 = j_lo + lane;
        const int j1 = j_lo + 32 + lane;
        const bool p0 = (j0 < j_hi);
        const bool p1 = (j1 < j_hi);
        if (p0) e0 = src[j0];
        if (p1) e1 = src[j1];

        // ---- chain B warm-up: t=6,7 (m0/m1 only) ----
        H4 c0B, c1B;
        {
            const int c6 = (pk[1] >> 16) & 0xFF;
            const int c7 = (pk[1] >> 24) & 0xFF;
            const char* r6 = Ms_lane + c6 * 768;
            const char* r7 = Ms_lane + c7 * 768;
            H4 m0_6 = *reinterpret_cast<const H4*>(r6);
            H4 m1_6 = *reinterpret_cast<const H4*>(r6 + 256);
            H4 m0_7 = *reinterpret_cast<const H4*>(r7);
            H4 m1_7 = *reinterpret_cast<const H4*>(r7 + 256);
            c1B = h4add(m1_7, m0_6);   // carry into t=8
            c0B = m0_7;
        }

        // ---- interleaved dual chains: A t=i, B t=i+8 ----
        H4 maxsA, c0A = zero, c1A = zero;
        H4 maxsB;
#pragma unroll
        for (int i = 0; i < 8; ++i) {
            {
                const int cc = (pk[i >> 2] >> ((i & 3) * 8)) & 0xFF;
                const char* rowp = Ms_lane + cc * 768;
                H4 m0 = *reinterpret_cast<const H4*>(rowp);
                H4 m1 = *reinterpret_cast<const H4*>(rowp + 256);
                H4 m2 = *reinterpret_cast<const H4*>(rowp + 512);
                H4 y  = h4add(m2, c1A);
                maxsA = (i == 0) ? y : h4max(maxsA, y);
                c1A = h4add(m1, c0A);
                c0A = m0;
            }
            {
                const int t  = i + 8;
                const int cc = (pk[t >> 2] >> ((t & 3) * 8)) & 0xFF;
                const char* rowp = Ms_lane + cc * 768;
                H4 m0 = *reinterpret_cast<const H4*>(rowp);
                H4 m1 = *reinterpret_cast<const H4*>(rowp + 256);
                H4 m2 = *reinterpret_cast<const H4*>(rowp + 512);
                H4 y  = h4add(m2, c1B);
                maxsB = (i == 0) ? y : h4max(maxsB, y);
                c1B = h4add(m1, c0B);
                c0B = m0;
            }
        }
        maxsB = h4max(maxsB, c1B);   // t = 16
        maxsB = h4max(maxsB, c0B);   // t = 17
        H4 maxs = h4max(maxsA, maxsB);

        // fp32 bias + relu + store
        float2 f0 = __half22float2(maxs.a);
        float2 f1 = __half22float2(maxs.b);
        float4 r;
        r.x = fmaxf(f0.x + b4.x, 0.f);
        r.y = fmaxf(f0.y + b4.y, 0.f);
        r.z = fmaxf(f1.x + b4.z, 0.f);
        r.w = fmaxf(f1.y + b4.w, 0.f);
        *reinterpret_cast<float4*>(out + (size_t)w * OUTW + o_base + lane * 4) = r;

        if (p0) dst[j0] = e0;
        if (p1) dst[j1] = e1;
    }
}

// ---------------------------------------------------------------------------
// Launch: build, then main with Programmatic Stream Serialization (PDL).
// ---------------------------------------------------------------------------
extern "C" void kernel_launch(void* const* d_in, const int* in_sizes, int n_in,
                              void* d_out, int out_size) {
    const int*   X        = (const int*)  d_in[0];   // [16384,16]
    const int*   X_word   = (const int*)  d_in[1];   // [16384]
    const float* char_emb = (const float*)d_in[2];   // [128,64]
    const float* conv_w   = (const float*)d_in[3];   // [256,64,3]
    const float* conv_b   = (const float*)d_in[4];   // [256]
    const float* word_emb = (const float*)d_in[5];   // [50000,300]
    float*       out      = (float*)d_out;           // [16384,556]

    build_tables_kernel<<<256, 128>>>(char_emb, conv_w);

    cudaFuncSetAttribute(wordchar_main_kernel,
                         cudaFuncAttributeMaxDynamicSharedMemorySize, SM_TOTAL);

    cudaLaunchConfig_t cfg = {};
    cfg.gridDim  = dim3(148, 2, 1);
    cfg.blockDim = dim3(640, 1, 1);
    cfg.dynamicSmemBytes = SM_TOTAL;
    cfg.stream = 0;
    cudaLaunchAttribute attrs[1];
    attrs[0].id = cudaLaunchAttributeProgrammaticStreamSerialization;
    attrs[0].val.programmaticStreamSerializationAllowed = 1;
    cfg.attrs = attrs;
    cfg.numAttrs = 1;
    cudaLaunchKernelEx(&cfg, wordchar_main_kernel,
                       X, X_word, conv_b, word_emb, out);
}

// round 15
// speedup vs baseline: 1.0789x; 1.0077x over previous
#include <cuda_runtime.h>
#include <cuda_fp16.h>

// Problem constants
#define NW      16384   // words
#define LCH     16      // chars per word
#define CEMB    64      // char emb dim
#define CO      256     // conv out channels
#define DEMB    300     // word emb dim
#define OUTW    556     // 256 + 300
#define OCHUNK  128     // channels per block (blockIdx.y in {0,1})
#define WPC     111     // words per CTA (148 * 111 >= 16384)
#define CONVW   16      // conv warps per CTA
#define COPYW   4       // copy warps per CTA (block = 640)

// Precomputed conv tables (fp16): M[k][c][o] = sum_e char_emb[c,e]*conv_w[o,e,k]
__device__ __half g_Mh[3 * 128 * 256];

// smem layout offsets (bytes)
#define SM_XPK    98304                    // WPC uint4 (packed chars)
#define SM_XW     (98304 + WPC * 16)       // WPC ints
#define SM_TOTAL  (SM_XW + WPC * 4)

// ---------------------------------------------------------------------------
// Kernel 1: build tables. grid = 256 (o), block = 128 (c).
// ---------------------------------------------------------------------------
__global__ void build_tables_kernel(const float* __restrict__ ce_w,
                                    const float* __restrict__ conv_w) {
    __shared__ float se[64 * 130];   // padded rows: no STS conflicts
    const int o = blockIdx.x;
    const int c = threadIdx.x;

    for (int i = threadIdx.x; i < 128 * 64; i += 128) {
        int cc = i >> 6;
        int e  = i & 63;
        se[e * 130 + cc] = ce_w[i];
    }
    __syncthreads();

    const float4* wp4 = reinterpret_cast<const float4*>(conv_w + o * (CEMB * 3));
    float a0 = 0.f, a1 = 0.f, a2 = 0.f;
#pragma unroll
    for (int g = 0; g < 16; ++g) {
        float4 f0 = wp4[3 * g + 0];
        float4 f1 = wp4[3 * g + 1];
        float4 f2 = wp4[3 * g + 2];
        float s0 = se[(4 * g + 0) * 130 + c];
        float s1 = se[(4 * g + 1) * 130 + c];
        float s2 = se[(4 * g + 2) * 130 + c];
        float s3 = se[(4 * g + 3) * 130 + c];
        a0 = fmaf(s0, f0.x, a0); a1 = fmaf(s0, f0.y, a1); a2 = fmaf(s0, f0.z, a2);
        a0 = fmaf(s1, f0.w, a0); a1 = fmaf(s1, f1.x, a1); a2 = fmaf(s1, f1.y, a2);
        a0 = fmaf(s2, f1.z, a0); a1 = fmaf(s2, f1.w, a1); a2 = fmaf(s2, f2.x, a2);
        a0 = fmaf(s3, f2.y, a0); a1 = fmaf(s3, f2.z, a1); a2 = fmaf(s3, f2.w, a2);
    }
    g_Mh[(0 * 128 + c) * 256 + o] = __float2half_rn(a0);
    g_Mh[(1 * 128 + c) * 256 + o] = __float2half_rn(a1);
    g_Mh[(2 * 128 + c) * 256 + o] = __float2half_rn(a2);
}

// ---------------------------------------------------------------------------
// Kernel 2: main. grid = (148, 2), block = 640, ~98.2 KB dyn smem, 2 CTAs/SM.
// WARP-SPECIALIZED: warps 0-15 = pure conv (LDS-only inner loop);
// warps 16-19 = wemb gather->store (all DRAM latency isolated here).
// ---------------------------------------------------------------------------
struct H4 { __half2 a, b; };

__device__ __forceinline__ H4 h4add(H4 x, H4 y) {
    H4 r; r.a = __hadd2(x.a, y.a); r.b = __hadd2(x.b, y.b); return r;
}
__device__ __forceinline__ H4 h4max(H4 x, H4 y) {
    H4 r; r.a = __hmax2(x.a, y.a); r.b = __hmax2(x.b, y.b); return r;
}

extern "C" __global__ void __launch_bounds__(640, 2)
wordchar_main_kernel(const int* __restrict__ X,
                     const int* __restrict__ Xword,
                     const float* __restrict__ conv_b,
                     const float* __restrict__ wemb,
                     float* __restrict__ out) {
    extern __shared__ __align__(16) char smem_raw[];
    uint4* xs_pk4 = reinterpret_cast<uint4*>(smem_raw + SM_XPK);
    unsigned* xs_pk = reinterpret_cast<unsigned*>(smem_raw + SM_XPK);
    int* xw_s = reinterpret_cast<int*>(smem_raw + SM_XW);

    const int half_id = blockIdx.y;
    const int o_base  = half_id * OCHUNK;

    const int base = blockIdx.x * WPC;
    const int cnt  = (NW - base < WPC) ? (NW - base) : WPC;

    // ---- staging: table via cp.async; chars/Xword in its shadow ----
    {
        const char* gbase = reinterpret_cast<const char*>(g_Mh);
        const unsigned sbase = (unsigned)__cvta_generic_to_shared(smem_raw);
        const int ntot4 = 128 * 48;            // 6144 uint4 (16B) chunks
        for (int i = threadIdx.x; i < ntot4; i += blockDim.x) {
            int c = i / 48;
            int s = i - c * 48;                // 48 uint4 per 768B char row
            int k = s >> 4;                    // 16 uint4 per k-slab
            int j = s & 15;
            const char* gsrc = gbase +
                (((size_t)(k * 128 + c) * 32 + half_id * 16 + j) * 16);
            asm volatile("cp.async.cg.shared.global [%0], [%1], 16;\n"
                         :: "r"(sbase + i * 16), "l"(gsrc));
        }
        asm volatile("cp.async.commit_group;\n" ::: "memory");

        const int4* X4 = reinterpret_cast<const int4*>(X);
        for (int i = threadIdx.x; i < cnt * 4; i += blockDim.x) {
            int4 xi = X4[base * 4 + i];        // coalesced
            xs_pk[i] = (unsigned)xi.x | ((unsigned)xi.y << 8) |
                       ((unsigned)xi.z << 16) | ((unsigned)xi.w << 24);
        }
        for (int i = threadIdx.x; i < cnt; i += blockDim.x)
            xw_s[i] = Xword[base + i];

        asm volatile("cp.async.wait_group 0;\n" ::: "memory");
    }
    __syncthreads();

    const int warp = threadIdx.x >> 5;
    const int lane = threadIdx.x & 31;

    const int j_lo = (half_id == 0) ? 0  : 38;
    const int j_hi = (half_id == 0) ? 38 : 75;

    if (warp >= CONVW) {
        // ================= copy warps: wemb gather -> out =================
        const int ja = j_lo + lane;
        const int jb = j_lo + 32 + lane;
        const bool pa = (ja < j_hi);
        const bool pb = (jb < j_hi);
        for (int wl = warp - CONVW; wl < cnt; wl += COPYW) {
            const int w  = base + wl;
            const int wi = xw_s[wl];
            const float4* src = reinterpret_cast<const float4*>(wemb + (size_t)wi * DEMB);
            float4* dst = reinterpret_cast<float4*>(out + (size_t)w * OUTW + CO);
            float4 a, b;
            if (pa) a = src[ja];
            if (pb) b = src[jb];
            if (pa) dst[ja] = a;
            if (pb) dst[jb] = b;
        }
        return;
    }

    // ==================== conv warps: pure LDS stream ====================
    const float4 b4 = *reinterpret_cast<const float4*>(conv_b + o_base + lane * 4);
    const char* Ms_lane = smem_raw + lane * 8;

    const H4 zero = { __float2half2_rn(0.f), __float2half2_rn(0.f) };

    for (int wl = warp; wl < cnt; wl += CONVW) {
        const int w = base + wl;

        // chars: one broadcast LDS.128
        uint4 pkv = xs_pk4[wl];
        unsigned pk[4] = { pkv.x, pkv.y, pkv.z, pkv.w };

        // ---- chain B warm-up: t=6,7 (m0/m1 only) ----
        H4 c0B, c1B;
        {
            const int c6 = (pk[1] >> 16) & 0xFF;
            const int c7 = (pk[1] >> 24) & 0xFF;
            const char* r6 = Ms_lane + c6 * 768;
            const char* r7 = Ms_lane + c7 * 768;
            H4 m0_6 = *reinterpret_cast<const H4*>(r6);
            H4 m1_6 = *reinterpret_cast<const H4*>(r6 + 256);
            H4 m0_7 = *reinterpret_cast<const H4*>(r7);
            H4 m1_7 = *reinterpret_cast<const H4*>(r7 + 256);
            c1B = h4add(m1_7, m0_6);   // carry into t=8
            c0B = m0_7;
        }

        // ---- interleaved dual chains: A t=i, B t=i+8 ----
        H4 maxsA, c0A = zero, c1A = zero;
        H4 maxsB;
#pragma unroll
        for (int i = 0; i < 8; ++i) {
            {
                const int cc = (pk[i >> 2] >> ((i & 3) * 8)) & 0xFF;
                const char* rowp = Ms_lane + cc * 768;
                H4 m0 = *reinterpret_cast<const H4*>(rowp);
                H4 m1 = *reinterpret_cast<const H4*>(rowp + 256);
                H4 m2 = *reinterpret_cast<const H4*>(rowp + 512);
                H4 y  = h4add(m2, c1A);
                maxsA = (i == 0) ? y : h4max(maxsA, y);
                c1A = h4add(m1, c0A);
                c0A = m0;
            }
            {
                const int t  = i + 8;
                const int cc = (pk[t >> 2] >> ((t & 3) * 8)) & 0xFF;
                const char* rowp = Ms_lane + cc * 768;
                H4 m0 = *reinterpret_cast<const H4*>(rowp);
                H4 m1 = *reinterpret_cast<const H4*>(rowp + 256);
                H4 m2 = *reinterpret_cast<const H4*>(rowp + 512);
                H4 y  = h4add(m2, c1B);
                maxsB = (i == 0) ? y : h4max(maxsB, y);
                c1B = h4add(m1, c0B);
                c0B = m0;
            }
        }
        maxsB = h4max(maxsB, c1B);   // t = 16
        maxsB = h4max(maxsB, c0B);   // t = 17
        H4 maxs = h4max(maxsA, maxsB);

        // fp32 bias + relu + store
        float2 f0 = __half22float2(maxs.a);
        float2 f1 = __half22float2(maxs.b);
        float4 r;
        r.x = fmaxf(f0.x + b4.x, 0.f);
        r.y = fmaxf(f0.y + b4.y, 0.f);
        r.z = fmaxf(f1.x + b4.z, 0.f);
        r.w = fmaxf(f1.y + b4.w, 0.f);
        *reinterpret_cast<float4*>(out + (size_t)w * OUTW + o_base + lane * 4) = r;
    }
}

// ---------------------------------------------------------------------------
// Launch
// ---------------------------------------------------------------------------
extern "C" void kernel_launch(void* const* d_in, const int* in_sizes, int n_in,
                              void* d_out, int out_size) {
    const int*   X        = (const int*)  d_in[0];   // [16384,16]
    const int*   X_word   = (const int*)  d_in[1];   // [16384]
    const float* char_emb = (const float*)d_in[2];   // [128,64]
    const float* conv_w   = (const float*)d_in[3];   // [256,64,3]
    const float* conv_b   = (const float*)d_in[4];   // [256]
    const float* word_emb = (const float*)d_in[5];   // [50000,300]
    float*       out      = (float*)d_out;           // [16384,556]

    build_tables_kernel<<<256, 128>>>(char_emb, conv_w);

    cudaFuncSetAttribute(wordchar_main_kernel,
                         cudaFuncAttributeMaxDynamicSharedMemorySize, SM_TOTAL);
    dim3 grid(148, 2);
    wordchar_main_kernel<<<grid, 640, SM_TOTAL>>>(X, X_word, conv_b, word_emb, out);
}